// round 1
// baseline (speedup 1.0000x reference)
#include <cuda_runtime.h>
#include <cstdint>
#include <cstddef>

#define VSZ 32000
#define TT 64
#define BB 32
#define HH 32
#define EE 200
#define NT (BB*TT)           // 2048 rows (b*T + t)
#define NVC 256              // vocab columns per block chunk
#define NCHUNK (VSZ/NVC)     // 125
#define GROUPS (NT/128)      // 16 task groups (128 tasks per block, 1 per lane)
#define LOG2E 1.4426950408889634f

// ---------------- scratch (static device arrays; no allocation) ----------------
__device__ float g_xproj[NT*HH];
__device__ float g_H[NT*HH];
__device__ float g_Spart[NT*NCHUNK];
__device__ float g_C[NT];
__device__ float g_Mpart[NT*NCHUNK];
__device__ int   g_Ipart[NT*NCHUNK];

// ---------------- packed f32x2 helpers (Blackwell FFMA2) ----------------
__device__ __forceinline__ unsigned long long ffma2(unsigned long long a, unsigned long long b, unsigned long long c){
    unsigned long long d;
    asm("fma.rn.f32x2 %0, %1, %2, %3;" : "=l"(d) : "l"(a), "l"(b), "l"(c));
    return d;
}
__device__ __forceinline__ unsigned long long fadd2(unsigned long long a, unsigned long long b){
    unsigned long long d;
    asm("add.rn.f32x2 %0, %1, %2;" : "=l"(d) : "l"(a), "l"(b));
    return d;
}
__device__ __forceinline__ unsigned long long packf2(float lo, float hi){
    unsigned long long d;
    asm("mov.b64 %0, {%1, %2};" : "=l"(d) : "f"(lo), "f"(hi));
    return d;
}
__device__ __forceinline__ float sumf2(unsigned long long a){
    float lo, hi;
    asm("mov.b64 {%0, %1}, %2;" : "=f"(lo), "=f"(hi) : "l"(a));
    return lo + hi;
}
__device__ __forceinline__ float ex2a(float x){
    float r; asm("ex2.approx.f32 %0, %1;" : "=f"(r) : "f"(x)); return r;
}
// accurate-enough tanh immune to -use_fast_math's tanh.approx (2^-11 would flip argmaxes)
__device__ __forceinline__ float tanh_acc(float x){
    float t = expf(2.0f * x);
    return (t - 1.0f) / (t + 1.0f);
}

// ---------------- K1: xproj[task][j] = Wi[j] . emb[y[task]] + bi[j] + bh[j] ----------------
__global__ void k_xproj(const int* __restrict__ y, const float* __restrict__ emb,
                        const float* __restrict__ Wi, const float* __restrict__ bi,
                        const float* __restrict__ bh){
    int task = blockIdx.x * 8 + (threadIdx.x >> 5);
    int j = threadIdx.x & 31;
    int yv = y[task];
    const float4* er = (const float4*)(emb + (size_t)yv * EE);
    const float4* wr = (const float4*)(Wi + (size_t)j * EE);
    float a0 = 0.f, a1 = 0.f, a2 = 0.f, a3 = 0.f;
#pragma unroll 10
    for (int i = 0; i < EE/4; i++){
        float4 e = er[i]; float4 w = wr[i];
        a0 += e.x * w.x; a1 += e.y * w.y; a2 += e.z * w.z; a3 += e.w * w.w;
    }
    g_xproj[task*HH + j] = (a0 + a1) + (a2 + a3) + bi[j] + bh[j];
}

// ---------------- K2: sequential recurrence, one warp per batch ----------------
__global__ void k_hchain(const float* __restrict__ enc, const float* __restrict__ Wh){
    int b = blockIdx.x;
    int j = threadIdx.x;  // 0..31
    float wh[HH];
#pragma unroll
    for (int k = 0; k < HH; k++) wh[k] = Wh[j*HH + k];
    __shared__ float hs[HH];
    hs[j] = enc[b*HH + j];
    __syncwarp();
    for (int t = 0; t < TT; t++){
        int row = b*TT + t;
        float a0 = g_xproj[row*HH + j], a1 = 0.f, a2 = 0.f, a3 = 0.f;
#pragma unroll
        for (int k = 0; k < HH; k += 4){
            a0 += wh[k]   * hs[k];
            a1 += wh[k+1] * hs[k+1];
            a2 += wh[k+2] * hs[k+2];
            a3 += wh[k+3] * hs[k+3];
        }
        float h = tanh_acc((a0 + a1) + (a2 + a3));
        __syncwarp();
        hs[j] = h;
        g_H[row*HH + j] = h;
        __syncwarp();
    }
}

// ---------------- K3a: sum of exp(logit) per (task, vchunk). Lane = task. ----------------
__global__ void __launch_bounds__(128) k_pass1(const float* __restrict__ Wo,
                                               const float* __restrict__ bo){
    __shared__ float sWo[NVC*HH];
    __shared__ float sbo[NVC];
    int tid = threadIdx.x;
    int task = blockIdx.x * 128 + tid;
    int v0 = blockIdx.y * NVC;

    // stage Wo chunk + bo chunk (bo pre-scaled by log2e)
    {
        const float4* src = (const float4*)(Wo + (size_t)v0 * HH);
        float4* dst = (float4*)sWo;
        for (int i = tid; i < NVC*HH/4; i += 128) dst[i] = src[i];
        for (int i = tid; i < NVC; i += 128) sbo[i] = bo[v0 + i] * LOG2E;
    }
    // h row in packed regs, pre-scaled by log2e so dot is already in log2 units
    unsigned long long h2[16];
    {
        const float4* hp = (const float4*)(g_H + (size_t)task * HH);
#pragma unroll
        for (int i = 0; i < 8; i++){
            float4 x = hp[i];
            h2[2*i]   = packf2(x.x * LOG2E, x.y * LOG2E);
            h2[2*i+1] = packf2(x.z * LOG2E, x.w * LOG2E);
        }
    }
    __syncthreads();

    float s = 0.f;
#pragma unroll 2
    for (int v = 0; v < NVC; v++){
        const ulonglong2* wp = (const ulonglong2*)(sWo + v*HH);
        unsigned long long a0 = packf2(sbo[v], 0.f);
        unsigned long long a1 = 0ull, a2 = 0ull, a3 = 0ull;
#pragma unroll
        for (int i = 0; i < 8; i++){
            ulonglong2 w = wp[i];
            if ((i & 1) == 0){ a0 = ffma2(h2[2*i], w.x, a0); a1 = ffma2(h2[2*i+1], w.y, a1); }
            else             { a2 = ffma2(h2[2*i], w.x, a2); a3 = ffma2(h2[2*i+1], w.y, a3); }
        }
        float l2 = sumf2(fadd2(fadd2(a0, a1), fadd2(a2, a3)));
        s += ex2a(l2);
    }
    g_Spart[task*NCHUNK + blockIdx.y] = s;
}

// ---------------- K4: C[task] = ln(sum of partials) ----------------
__global__ void k_lse(){
    int task = blockIdx.x * blockDim.x + threadIdx.x;
    if (task < NT){
        float s = 0.f;
        for (int c = 0; c < NCHUNK; c++) s += g_Spart[task*NCHUNK + c];
        g_C[task] = logf(s);
    }
}

// ---------------- K3b: logprob = logit - C, coalesced write + fp32 argmax ----------------
__global__ void __launch_bounds__(128) k_pass2(const float* __restrict__ Wo,
                                               const float* __restrict__ bo,
                                               float* __restrict__ out){
    __shared__ float sWo[NVC*HH];
    __shared__ float sbo[NVC];
    __shared__ float tile[4][32][17];   // per-warp transpose tile (stride 17: conflict-free writes)
    int tid = threadIdx.x;
    int w = tid >> 5, lane = tid & 31;
    int task = blockIdx.x * 128 + tid;
    int v0 = blockIdx.y * NVC;

    {
        const float4* src = (const float4*)(Wo + (size_t)v0 * HH);
        float4* dst = (float4*)sWo;
        for (int i = tid; i < NVC*HH/4; i += 128) dst[i] = src[i];
        for (int i = tid; i < NVC; i += 128) sbo[i] = bo[v0 + i];
    }
    unsigned long long h2[16];
    {
        const float4* hp = (const float4*)(g_H + (size_t)task * HH);
#pragma unroll
        for (int i = 0; i < 8; i++){
            float4 x = hp[i];
            h2[2*i]   = packf2(x.x, x.y);
            h2[2*i+1] = packf2(x.z, x.w);
        }
    }
    float negC = -g_C[task];
    __syncthreads();

    float mx = -3.4e38f;
    int mi = 0;
    // flush geometry: lanes 0..15 -> row rr=0 cols 0..15, lanes 16..31 -> row rr=1
    int rr = lane >> 4, cc = lane & 15;
    float* outrow = out + (size_t)(blockIdx.x*128 + w*32 + rr) * VSZ + v0 + cc;

    for (int v = 0; v < NVC; v++){
        const ulonglong2* wp = (const ulonglong2*)(sWo + v*HH);
        unsigned long long a0 = packf2(sbo[v], negC);   // bo - C folded into accumulator init
        unsigned long long a1 = 0ull, a2 = 0ull, a3 = 0ull;
#pragma unroll
        for (int i = 0; i < 8; i++){
            ulonglong2 wv = wp[i];
            if ((i & 1) == 0){ a0 = ffma2(h2[2*i], wv.x, a0); a1 = ffma2(h2[2*i+1], wv.y, a1); }
            else             { a2 = ffma2(h2[2*i], wv.x, a2); a3 = ffma2(h2[2*i+1], wv.y, a3); }
        }
        float lp = sumf2(fadd2(fadd2(a0, a1), fadd2(a2, a3)));
        tile[w][lane][v & 15] = lp;
        if (lp > mx){ mx = lp; mi = v0 + v; }   // strict > : first occurrence wins (matches argmax)
        if ((v & 15) == 15){
            __syncwarp();
            float* tp = &tile[w][0][0];
            float* op = outrow + (v - 15);
#pragma unroll 4
            for (int r = 0; r < 32; r += 2){
                op[(size_t)r * VSZ] = tp[(r + rr)*17 + cc];
            }
            __syncwarp();
        }
    }
    g_Mpart[task*NCHUNK + blockIdx.y] = mx;
    g_Ipart[task*NCHUNK + blockIdx.y] = mi;
}

// ---------------- K5: combine argmax partials (chunk-ascending, strict >) ----------------
__global__ void k_argmax(float* __restrict__ preds){
    int task = blockIdx.x * blockDim.x + threadIdx.x;
    if (task < NT){
        float mx = -3.4e38f; int mi = 0;
        for (int c = 0; c < NCHUNK; c++){
            float m = g_Mpart[task*NCHUNK + c];
            if (m > mx){ mx = m; mi = g_Ipart[task*NCHUNK + c]; }
        }
        preds[task] = (float)mi;
    }
}

// ---------------- launch ----------------
extern "C" void kernel_launch(void* const* d_in, const int* in_sizes, int n_in,
                              void* d_out, int out_size){
    const int*   y   = (const int*)  d_in[0];
    const float* enc = (const float*)d_in[1];
    const float* emb = (const float*)d_in[2];
    const float* Wi  = (const float*)d_in[3];
    const float* bi  = (const float*)d_in[4];
    const float* Wh  = (const float*)d_in[5];
    const float* bh  = (const float*)d_in[6];
    const float* Wo  = (const float*)d_in[7];
    const float* bo  = (const float*)d_in[8];
    float* out = (float*)d_out;

    k_xproj<<<NT/8, 256>>>(y, emb, Wi, bi, bh);
    k_hchain<<<BB, 32>>>(enc, Wh);
    k_pass1<<<dim3(GROUPS, NCHUNK), 128>>>(Wo, bo);
    k_lse<<<8, 256>>>();
    k_pass2<<<dim3(GROUPS, NCHUNK), 128>>>(Wo, bo, out);
    if ((long long)out_size > (long long)NT * VSZ){
        k_argmax<<<2, 1024>>>(out + (size_t)NT * VSZ);
    }
}